// round 16
// baseline (speedup 1.0000x reference)
#include <cuda_runtime.h>
#include <cuda_bf16.h>
#include <math.h>
#include <stdint.h>

#define PIX 25088           // 8*56*56
#define NWIN 392            // 8*49

// ---------------- device scratch ----------------
__device__ __align__(128) float g_qkv [PIX*768];          // qkv fp32, window-major rows
__device__ __align__(128) __nv_bfloat16 g_ahi[PIX*256];   // generic A operand hi (reused)
__device__ __align__(128) __nv_bfloat16 g_alo[PIX*256];   // generic A operand lo
__device__ __align__(128) float g_xbar[NWIN*256];
__device__ __align__(128) float g_qwin[NWIN*256];
__device__ __align__(128) float g_kwin[NWIN*256];
__device__ __align__(128) int   g_ridx[NWIN*4];
__device__ __align__(128) float g_lepe[PIX*256];          // window-major
__device__ __align__(128) float g_x2  [PIX*256];          // image-major residual stream
__device__ __align__(128) __nv_bfloat16 g_hhi[PIX*1024];  // mlp hidden hi
__device__ __align__(128) __nv_bfloat16 g_hlo[PIX*1024];  // mlp hidden lo
__device__ __align__(128) __nv_bfloat16 g_wth[786432];    // transposed weights hi [N][K]
__device__ __align__(128) __nv_bfloat16 g_wtl[786432];    // transposed weights lo
#define OFF_QKV 0
#define OFF_WO  196608
#define OFF_M1  262144
#define OFF_M2  524288

// ---------------- layout maps ----------------
__device__ __forceinline__ int img2win(int pix){
    int n = pix / 3136, r = pix % 3136;
    int y = r / 56, x = r % 56;
    return (n*49 + (y>>3)*7 + (x>>3))*64 + ((y&7)<<3) + (x&7);
}
__device__ __forceinline__ int win2img(int rw){
    int n = rw / 3136, r = rw % 3136;
    int p = r >> 6, q = r & 63;
    int y = ((p/7)<<3) + (q>>3), x = ((p%7)<<3) + (q&7);
    return n*3136 + y*56 + x;
}

// ---------------- helpers ----------------
__device__ __forceinline__ uint32_t smem_u32(const void* p){
    uint32_t a;
    asm("{ .reg .u64 t; cvta.to.shared.u64 t, %1; cvt.u32.u64 %0, t; }" : "=r"(a) : "l"(p));
    return a;
}
__device__ __forceinline__ void cp16(uint32_t saddr, const void* gaddr){
    asm volatile("cp.async.cg.shared.global [%0], [%1], 16;" :: "r"(saddr), "l"(gaddr));
}
__device__ __forceinline__ void ldmA(uint32_t* a, uint32_t addr){
    asm volatile("ldmatrix.sync.aligned.m8n8.x4.shared.b16 {%0,%1,%2,%3}, [%4];"
        : "=r"(a[0]),"=r"(a[1]),"=r"(a[2]),"=r"(a[3]) : "r"(addr));
}
__device__ __forceinline__ void ldmB(uint32_t* b, uint32_t addr){
    asm volatile("ldmatrix.sync.aligned.m8n8.x2.shared.b16 {%0,%1}, [%2];"
        : "=r"(b[0]),"=r"(b[1]) : "r"(addr));
}
__device__ __forceinline__ void mma16816(float* c, const uint32_t* a, const uint32_t* b){
    asm volatile("mma.sync.aligned.m16n8k16.row.col.f32.bf16.bf16.f32 "
        "{%0,%1,%2,%3}, {%4,%5,%6,%7}, {%8,%9}, {%0,%1,%2,%3};"
        : "+f"(c[0]),"+f"(c[1]),"+f"(c[2]),"+f"(c[3])
        : "r"(a[0]),"r"(a[1]),"r"(a[2]),"r"(a[3]), "r"(b[0]),"r"(b[1]));
}
__device__ __forceinline__ uint32_t packbf2(__nv_bfloat16 a, __nv_bfloat16 b){
    return (uint32_t)__bfloat16_as_ushort(a) | ((uint32_t)__bfloat16_as_ushort(b) << 16);
}
__device__ __forceinline__ void split8(const float* v, uint4& uh, uint4& ul){
    __nv_bfloat16 h[8], l[8];
    #pragma unroll
    for (int j = 0; j < 8; j++){
        h[j] = __float2bfloat16(v[j]);
        l[j] = __float2bfloat16(v[j] - __bfloat162float(h[j]));
    }
    uh = make_uint4(packbf2(h[0],h[1]), packbf2(h[2],h[3]), packbf2(h[4],h[5]), packbf2(h[6],h[7]));
    ul = make_uint4(packbf2(l[0],l[1]), packbf2(l[2],l[3]), packbf2(l[4],l[5]), packbf2(l[6],l[7]));
}

// ---------------- LayerNorm -> bf16 hi/lo ----------------
template<bool REMAP>
__global__ void ln_kernel(const float* __restrict__ in, const float* __restrict__ g,
                          const float* __restrict__ b,
                          __nv_bfloat16* __restrict__ oh, __nv_bfloat16* __restrict__ ol){
    int warp = threadIdx.x >> 5, lane = threadIdx.x & 31;
    int pix = blockIdx.x * 8 + warp;
    const float* row = in + (size_t)pix * 256;
    int c0 = lane * 8;
    float4 v0 = *(const float4*)(row + c0);
    float4 v1 = *(const float4*)(row + c0 + 4);
    float vals[8] = {v0.x,v0.y,v0.z,v0.w,v1.x,v1.y,v1.z,v1.w};
    float s = 0.f, ss = 0.f;
    #pragma unroll
    for (int u = 0; u < 8; u++){ s += vals[u]; ss += vals[u]*vals[u]; }
    #pragma unroll
    for (int o = 16; o; o >>= 1){
        s  += __shfl_xor_sync(0xffffffffu, s,  o);
        ss += __shfl_xor_sync(0xffffffffu, ss, o);
    }
    float mu  = s * (1.f/256.f);
    float var = ss * (1.f/256.f) - mu*mu;
    float inv = rsqrtf(var + 1e-6f);
    int orow = REMAP ? img2win(pix) : pix;
    float ov[8];
    #pragma unroll
    for (int u = 0; u < 8; u++) ov[u] = (vals[u]-mu)*inv*g[c0+u] + b[c0+u];
    uint4 uh, ul;
    split8(ov, uh, ul);
    *(uint4*)&oh[(size_t)orow*256 + c0] = uh;
    *(uint4*)&ol[(size_t)orow*256 + c0] = ul;
}

// ---------------- fused weight transpose + split (ALL matrices, one launch) -------
__global__ void wtrans_all_kernel(const float* __restrict__ qkv_w, const float* __restrict__ wo_w,
                                  const float* __restrict__ m1_w,  const float* __restrict__ m2_w){
    __shared__ float t[32][33];
    int b = blockIdx.x;
    const float* w; int K, N, off;
    if (b < 192)      { w = qkv_w;       K = 256;  N = 768;  off = OFF_QKV; }
    else if (b < 256) { b -= 192; w = wo_w; K = 256; N = 256; off = OFF_WO; }
    else if (b < 512) { b -= 256; w = m1_w; K = 256; N = 1024; off = OFF_M1; }
    else              { b -= 512; w = m2_w; K = 1024; N = 256; off = OFF_M2; }
    int ntiles = N / 32;
    int n0 = (b % ntiles) * 32, k0 = (b / ntiles) * 32;
    int tx = threadIdx.x, ty = threadIdx.y;
    for (int r = ty; r < 32; r += 8) t[r][tx] = w[(size_t)(k0+r)*N + n0+tx];
    __syncthreads();
    for (int r = ty; r < 32; r += 8){
        float v = t[tx][r];
        __nv_bfloat16 h = __float2bfloat16(v);
        g_wth[off + (size_t)(n0+r)*K + k0+tx] = h;
        g_wtl[off + (size_t)(n0+r)*K + k0+tx] = __float2bfloat16(v - __bfloat162float(h));
    }
}

// ---------------- window mean of x (hi+lo, exact routing path) ----------------
__global__ void winmeanx_kernel(){
    int np = blockIdx.x, c = threadIdx.x;
    float s = 0.f;
    #pragma unroll 4
    for (int r = 0; r < 64; r++){
        size_t i = (size_t)(np*64+r)*256 + c;
        s += __bfloat162float(g_ahi[i]) + __bfloat162float(g_alo[i]);
    }
    g_xbar[np*256 + c] = s * (1.f/64.f);
}

// ---------------- q_win/k_win: 8 windows per block, q/k split over grid.y ----------
__global__ void winproj_kernel(const float* __restrict__ qkv_w, const float* __restrict__ qkv_b){
    __shared__ float sx[8][256];
    int b0 = blockIdx.x * 8;
    int qk = blockIdx.y;              // 0 = q, 1 = k
    int c = threadIdx.x;
    #pragma unroll
    for (int j = 0; j < 8; j++) sx[j][c] = g_xbar[(b0+j)*256 + c];
    __syncthreads();
    float bb = qkv_b[qk*256 + c];
    float a[8];
    #pragma unroll
    for (int j = 0; j < 8; j++) a[j] = bb;
    for (int d = 0; d < 256; d++){
        float wv = qkv_w[d*768 + qk*256 + c];
        #pragma unroll
        for (int j = 0; j < 8; j++) a[j] += sx[j][d]*wv;
    }
    float* outp = qk ? g_kwin : g_qwin;
    #pragma unroll
    for (int j = 0; j < 8; j++) outp[(b0+j)*256 + c] = a[j];
}

// ---------------- logits + top-4 (one block per window) ----------------
__global__ void logit_topk_kernel(){
    __shared__ float sq[256];
    __shared__ float sl[64];
    int np = blockIdx.x, n = np / 49;
    int tid = threadIdx.x;
    sq[tid] = g_qwin[np*256 + tid];
    if (tid < 64) sl[tid] = -1e30f;
    __syncthreads();
    int t = tid >> 2, part = tid & 3;
    int tc = (t < 49) ? t : 48;
    const float* kr = &g_kwin[(size_t)(n*49 + tc)*256 + part*64];
    float acc = 0.f;
    #pragma unroll 8
    for (int c = 0; c < 64; c++) acc += sq[part*64 + c] * kr[c];
    acc += __shfl_xor_sync(0xffffffffu, acc, 1);
    acc += __shfl_xor_sync(0xffffffffu, acc, 2);
    if (part == 0 && t < 49) sl[t] = acc * 0.0625f;
    __syncthreads();
    if (tid == 0){
        float bv[4] = {-1e30f,-1e30f,-1e30f,-1e30f};
        int   bi[4] = {0,0,0,0};
        for (int k = 0; k < 49; k++){
            float v = sl[k];
            if (v > bv[3]){
                int pos = 3;
                while (pos > 0 && v > bv[pos-1]) pos--;
                for (int sft = 3; sft > pos; sft--){ bv[sft]=bv[sft-1]; bi[sft]=bi[sft-1]; }
                bv[pos] = v; bi[pos] = k;
            }
        }
        #pragma unroll
        for (int s = 0; s < 4; s++) g_ridx[np*4 + s] = bi[s];
    }
}

// ---------------- lepe: 5x5 depthwise conv, smem-halo tiled ----------------
__global__ void __launch_bounds__(256) lepe_kernel(const float* __restrict__ w, const float* __restrict__ b){
    __shared__ float halo[144*68];
    __shared__ float ws[25*64];
    __shared__ float wb[64];
    int wi = blockIdx.x;
    int cg = blockIdx.y;
    int n  = blockIdx.z;
    int wy = wi / 7, wx = wi % 7;
    int tid = threadIdx.x;
    for (int i = tid; i < 1600; i += 256)
        ws[i] = w[(i>>6)*256 + cg*64 + (i&63)];
    if (tid < 64) wb[tid] = b[cg*64 + tid];
    for (int i = tid; i < 2304; i += 256){
        int hp = i >> 4, cs = i & 15;
        int hy = hp / 12, hx = hp % 12;
        int y = wy*8 - 2 + hy, x = wx*8 - 2 + hx;
        float4 v = make_float4(0.f,0.f,0.f,0.f);
        if ((unsigned)y < 56u && (unsigned)x < 56u){
            int rw = ((n*49 + (y>>3)*7 + (x>>3))<<6) + ((y&7)<<3) + (x&7);
            v = *(const float4*)&g_qkv[(size_t)rw*768 + 512 + cg*64 + cs*4];
        }
        *(float4*)&halo[hp*68 + cs*4] = v;
    }
    __syncthreads();
    int p = tid >> 2, q = tid & 3;
    int py = p >> 3, px = p & 7;
    float acc[16];
    #pragma unroll
    for (int j = 0; j < 16; j++) acc[j] = wb[q*16 + j];
    #pragma unroll
    for (int ky = 0; ky < 5; ky++)
        #pragma unroll
        for (int kx = 0; kx < 5; kx++){
            const float* hp2 = &halo[((py+ky)*12 + px+kx)*68 + q*16];
            const float* wp  = &ws[(ky*5+kx)*64 + q*16];
            #pragma unroll
            for (int j = 0; j < 16; j++) acc[j] += hp2[j]*wp[j];
        }
    int rw = ((n*49 + wy*7 + wx)<<6) + (py<<3) + px;
    float* outp = &g_lepe[(size_t)rw*256 + cg*64 + q*16];
    #pragma unroll
    for (int j = 0; j < 4; j++)
        *(float4*)&outp[j*4] = make_float4(acc[j*4],acc[j*4+1],acc[j*4+2],acc[j*4+3]);
}

// ---------------- attention: register-tiled, fused lepe-add + bf16 split ----------
#define ATT_ST 34
#define ATT_SMEM ((64*ATT_ST + 2*256*ATT_ST + 64*68)*4)   // 95744 B
__global__ void __launch_bounds__(256,2) attn_kernel(){
    int np = blockIdx.x;
    int m  = blockIdx.y;
    int n  = np / 49;
    int tid = threadIdx.x;
    extern __shared__ float sm[];
    float* sq = sm;
    float* sk = sq + 64*ATT_ST;
    float* sv = sk + 256*ATT_ST;
    float* sp = sv + 256*ATT_ST;
    int base = np * 64;

    for (int idx = tid; idx < 2048; idx += 256){
        int r = idx >> 5, d = idx & 31;
        sq[r*ATT_ST + d] = g_qkv[(size_t)(base+r)*768 + m*32 + d];
    }
    #pragma unroll
    for (int s4 = 0; s4 < 4; s4++){
        int wsel = g_ridx[np*4 + s4];
        int sb = (n*49 + wsel) * 64;
        for (int idx = tid; idx < 2048; idx += 256){
            int r = idx >> 5, d = idx & 31;
            int kk = s4*64 + r;
            sk[kk*ATT_ST + d] = g_qkv[(size_t)(sb+r)*768 + 256 + m*32 + d];
            sv[kk*ATT_ST + d] = g_qkv[(size_t)(sb+r)*768 + 512 + m*32 + d];
        }
    }
    __syncthreads();

    const int rowg = tid >> 3;
    const int colg = tid & 7;
    const int r0 = rowg*2, r1 = r0 + 1;

    float sc[2][32];
    #pragma unroll
    for (int j = 0; j < 32; j++){ sc[0][j] = 0.f; sc[1][j] = 0.f; }
    for (int cc = 0; cc < 16; cc++){
        float2 q0 = *(float2*)&sq[r0*ATT_ST + cc*2];
        float2 q1 = *(float2*)&sq[r1*ATT_ST + cc*2];
        #pragma unroll
        for (int j = 0; j < 32; j++){
            float2 kv = *(float2*)&sk[(j*8+colg)*ATT_ST + cc*2];
            sc[0][j] += q0.x*kv.x + q0.y*kv.y;
            sc[1][j] += q1.x*kv.x + q1.y*kv.y;
        }
    }
    float mx0 = -1e30f, mx1 = -1e30f;
    #pragma unroll
    for (int j = 0; j < 32; j++){
        sc[0][j] *= 0.0625f; sc[1][j] *= 0.0625f;
        mx0 = fmaxf(mx0, sc[0][j]); mx1 = fmaxf(mx1, sc[1][j]);
    }
    #pragma unroll
    for (int o = 4; o; o >>= 1){
        mx0 = fmaxf(mx0, __shfl_xor_sync(0xffffffffu, mx0, o));
        mx1 = fmaxf(mx1, __shfl_xor_sync(0xffffffffu, mx1, o));
    }
    float s0 = 0.f, s1 = 0.f;
    #pragma unroll
    for (int j = 0; j < 32; j++){
        sc[0][j] = expf(sc[0][j] - mx0); s0 += sc[0][j];
        sc[1][j] = expf(sc[1][j] - mx1); s1 += sc[1][j];
    }
    #pragma unroll
    for (int o = 4; o; o >>= 1){
        s0 += __shfl_xor_sync(0xffffffffu, s0, o);
        s1 += __shfl_xor_sync(0xffffffffu, s1, o);
    }
    float i0 = 1.f/s0, i1 = 1.f/s1;
    #pragma unroll
    for (int j = 0; j < 32; j++){ sc[0][j] *= i0; sc[1][j] *= i1; }

    const int chg = (tid >> 1) & 3;
    const int ksp = tid & 1;
    float oa[2][8];
    #pragma unroll
    for (int j = 0; j < 8; j++){ oa[0][j] = 0.f; oa[1][j] = 0.f; }

    #pragma unroll
    for (int c = 0; c < 4; c++){
        __syncthreads();
        #pragma unroll
        for (int jj = 0; jj < 8; jj++){
            int kl = jj*8 + colg;
            sp[r0*68 + kl] = sc[0][c*8 + jj];
            sp[r1*68 + kl] = sc[1][c*8 + jj];
        }
        __syncthreads();
        #pragma unroll 8
        for (int kk = 0; kk < 32; kk++){
            int kl = kk*2 + ksp;
            float p0 = sp[r0*68 + kl];
            float p1 = sp[r1*68 + kl];
            const float* vr = &sv[(c*64 + kl)*ATT_ST + chg*8];
            #pragma unroll
            for (int j2 = 0; j2 < 4; j2++){
                float2 vv = *(float2*)&vr[j2*2];
                oa[0][j2*2]   += p0*vv.x; oa[0][j2*2+1] += p0*vv.y;
                oa[1][j2*2]   += p1*vv.x; oa[1][j2*2+1] += p1*vv.y;
            }
        }
    }
    #pragma unroll
    for (int i2 = 0; i2 < 2; i2++)
        #pragma unroll
        for (int j = 0; j < 8; j++)
            oa[i2][j] += __shfl_xor_sync(0xffffffffu, oa[i2][j], 1);

    if (ksp == 0){
        #pragma unroll
        for (int i2 = 0; i2 < 2; i2++){
            int row = base + r0 + i2;
            int ch0 = m*32 + chg*8;
            const float* lp = &g_lepe[(size_t)row*256 + ch0];
            float v[8];
            #pragma unroll
            for (int j = 0; j < 8; j++) v[j] = oa[i2][j] + lp[j];
            uint4 uh, ul;
            split8(v, uh, ul);
            *(uint4*)&g_ahi[(size_t)row*256 + ch0] = uh;
            *(uint4*)&g_alo[(size_t)row*256 + ch0] = ul;
        }
    }
}

// ---------------- mma.sync split-bf16 GEMM: merged 3-pass w/ fragment reuse -------
// Per ks-step each unique fragment set (Ahi/Alo/Bhi/Blo) is loaded ONCE:
//   ldm Ahi, Bhi -> mma(Ahi,Bhi); ldm Blo -> mma(Ahi,Blo); ldm Alo -> mma(Alo,Bhi)
// 16 ldmatrix (was 24) per ks; peak live regs ~112 -> no spills at the 128 cap.
#define LDH 40
#define MG_TILE (128*LDH*2)          // 10240 B per tile
#define MG_STAGE (4*MG_TILE)         // 40960 B
#define MG_SMEM (2*MG_STAGE)         // 81920 B
template<int MODE>
__global__ void __launch_bounds__(256,2) mgemm_kernel(
    const __nv_bfloat16* __restrict__ Ahi, const __nv_bfloat16* __restrict__ Alo,
    const __nv_bfloat16* __restrict__ Bhi, const __nv_bfloat16* __restrict__ Blo,
    const float* __restrict__ bias, const float* __restrict__ res,
    float* __restrict__ outf, __nv_bfloat16* __restrict__ outh, __nv_bfloat16* __restrict__ outl,
    int N, int K)
{
    extern __shared__ __align__(128) char dsm[];
    const uint32_t sbase = smem_u32(dsm);
    const int tid = threadIdx.x, w = tid >> 5, lane = tid & 31;
    const int m0 = blockIdx.y * 128, n0 = blockIdx.x * 128;
    const int wm = (w >> 2) * 64, wn = (w & 3) * 32;
    const int kch = K / 32;

    float acc[4][4][4];
    #pragma unroll
    for (int i = 0; i < 4; i++)
        #pragma unroll
        for (int j = 0; j < 4; j++)
            #pragma unroll
            for (int q = 0; q < 4; q++) acc[i][j][q] = 0.f;

    const int rA = tid >> 2;
    const int sg = (tid & 3) * 8;

    auto issue = [&](int c, int s){
        int ko = c * 32;
        uint32_t st = sbase + s*MG_STAGE;
        uint32_t so0 = (uint32_t)(rA*LDH + sg) * 2;
        uint32_t so1 = (uint32_t)((64+rA)*LDH + sg) * 2;
        cp16(st + so0,             Ahi + (size_t)(m0+rA)*K + ko + sg);
        cp16(st + so1,             Ahi + (size_t)(m0+64+rA)*K + ko + sg);
        cp16(st + MG_TILE + so0,   Alo + (size_t)(m0+rA)*K + ko + sg);
        cp16(st + MG_TILE + so1,   Alo + (size_t)(m0+64+rA)*K + ko + sg);
        cp16(st + 2*MG_TILE + so0, Bhi + (size_t)(n0+rA)*K + ko + sg);
        cp16(st + 2*MG_TILE + so1, Bhi + (size_t)(n0+64+rA)*K + ko + sg);
        cp16(st + 3*MG_TILE + so0, Blo + (size_t)(n0+rA)*K + ko + sg);
        cp16(st + 3*MG_TILE + so1, Blo + (size_t)(n0+64+rA)*K + ko + sg);
        asm volatile("cp.async.commit_group;");
    };

    issue(0, 0);

    for (int c = 0; c < kch; c++){
        int s = c & 1;
        if (c + 1 < kch){
            issue(c+1, s ^ 1);
            asm volatile("cp.async.wait_group 1;");
        } else {
            asm volatile("cp.async.wait_group 0;");
        }
        __syncthreads();

        uint32_t st = sbase + s*MG_STAGE;
        #pragma unroll
        for (int ks = 0; ks < 2; ks++){
            const int kk = ks * 16;
            const uint32_t aoff = (uint32_t)((wm + (lane & 15))*LDH + kk + ((lane >> 4) & 1)*8) * 2;
            const uint32_t boff = (uint32_t)((wn + (lane & 7))*LDH + kk + ((lane >> 3) & 1)*8) * 2;

            uint32_t afr[4][4];        // Ahi fragments (live through pass 0 and 1)
            uint32_t bhi[4][2];        // Bhi fragments (live through pass 0 and 2)
            uint32_t tfr[4][4];        // temp: Blo (as [4][2] use) then Alo
            // pass 0: Ahi x Bhi
            #pragma unroll
            for (int mt = 0; mt < 4; mt++) ldmA(afr[mt], st + aoff + mt*16*LDH*2);
            #pragma unroll
            for (int nt = 0; nt < 4; nt++) ldmB(bhi[nt], st + 2*MG_TILE + boff + nt*8*LDH*2);
            #pragma unroll
            for (int mt = 0; mt < 4; mt++)
                #pragma unroll
                for (int nt = 0; nt < 4; nt++)
                    mma16816(acc[mt][nt], afr[mt], bhi[nt]);
            // pass 1: Ahi x Blo (Blo into tfr low halves)
            #pragma unroll
            for (int nt = 0; nt < 4; nt++) ldmB(&tfr[nt][0], st + 3*MG_TILE + boff + nt*8*LDH*2);
            #pragma unroll
            for (int mt = 0; mt < 4; mt++)
                #pragma unroll
                for (int nt = 0; nt < 4; nt++)
                    mma16816(acc[mt][nt], afr[mt], &tfr[nt][0]);
            // pass 2: Alo x Bhi (Alo reuses afr storage via tfr)
            #pragma unroll
            for (int mt = 0; mt < 4; mt++) ldmA(afr[mt], st + MG_TILE + aoff + mt*16*LDH*2);
            #pragma unroll
            for (int mt = 0; mt < 4; mt++)
                #pragma unroll
                for (int nt = 0; nt < 4; nt++)
                    mma16816(acc[mt][nt], afr[mt], bhi[nt]);
        }
        __syncthreads();
    }

    #pragma unroll
    for (int mt = 0; mt < 4; mt++){
        int r0 = m0 + wm + mt*16 + (lane >> 2);
        int r1 = r0 + 8;
        int o0 = (MODE == 1) ? win2img(r0) : r0;
        int o1 = (MODE == 1) ? win2img(r1) : r1;
        #pragma unroll
        for (int nt = 0; nt < 4; nt++){
            int col = n0 + wn + nt*8 + (lane & 3)*2;
            float b0 = bias[col], b1 = bias[col+1];
            float v00 = acc[mt][nt][0] + b0, v01 = acc[mt][nt][1] + b1;
            float v10 = acc[mt][nt][2] + b0, v11 = acc[mt][nt][3] + b1;
            if (MODE == 2){
                v00 = 0.5f*v00*(1.f + erff(v00*0.70710678118654752f));
                v01 = 0.5f*v01*(1.f + erff(v01*0.70710678118654752f));
                v10 = 0.5f*v10*(1.f + erff(v10*0.70710678118654752f));
                v11 = 0.5f*v11*(1.f + erff(v11*0.70710678118654752f));
                __nv_bfloat16 h00 = __float2bfloat16(v00), h01 = __float2bfloat16(v01);
                __nv_bfloat16 h10 = __float2bfloat16(v10), h11 = __float2bfloat16(v11);
                *(uint32_t*)&outh[(size_t)o0*N + col] = packbf2(h00, h01);
                *(uint32_t*)&outh[(size_t)o1*N + col] = packbf2(h10, h11);
                *(uint32_t*)&outl[(size_t)o0*N + col] = packbf2(
                    __float2bfloat16(v00 - __bfloat162float(h00)),
                    __float2bfloat16(v01 - __bfloat162float(h01)));
                *(uint32_t*)&outl[(size_t)o1*N + col] = packbf2(
                    __float2bfloat16(v10 - __bfloat162float(h10)),
                    __float2bfloat16(v11 - __bfloat162float(h11)));
            } else {
                if (MODE == 1 || MODE == 3){
                    v00 += res[(size_t)o0*N + col];   v01 += res[(size_t)o0*N + col + 1];
                    v10 += res[(size_t)o1*N + col];   v11 += res[(size_t)o1*N + col + 1];
                }
                *(float2*)&outf[(size_t)o0*N + col] = make_float2(v00, v01);
                *(float2*)&outf[(size_t)o1*N + col] = make_float2(v10, v11);
            }
        }
    }
}

// ---------------- launch ----------------
extern "C" void kernel_launch(void* const* d_in, const int* in_sizes, int n_in,
                              void* d_out, int out_size)
{
    const float* x      = (const float*)d_in[0];
    const float* ln1_g  = (const float*)d_in[1];
    const float* ln1_b  = (const float*)d_in[2];
    const float* qkv_w  = (const float*)d_in[3];
    const float* qkv_b  = (const float*)d_in[4];
    const float* lepe_w = (const float*)d_in[5];
    const float* lepe_b = (const float*)d_in[6];
    const float* wo_w   = (const float*)d_in[7];
    const float* wo_b   = (const float*)d_in[8];
    const float* ln2_g  = (const float*)d_in[9];
    const float* ln2_b  = (const float*)d_in[10];
    const float* mlp_w1 = (const float*)d_in[11];
    const float* mlp_b1 = (const float*)d_in[12];
    const float* mlp_w2 = (const float*)d_in[13];
    const float* mlp_b2 = (const float*)d_in[14];
    float* out = (float*)d_out;

    float *p_qkv, *p_x2;
    __nv_bfloat16 *p_ahi, *p_alo, *p_hhi, *p_hlo, *p_wth, *p_wtl;
    cudaGetSymbolAddress((void**)&p_qkv, g_qkv);
    cudaGetSymbolAddress((void**)&p_x2,  g_x2);
    cudaGetSymbolAddress((void**)&p_ahi, g_ahi);
    cudaGetSymbolAddress((void**)&p_alo, g_alo);
    cudaGetSymbolAddress((void**)&p_hhi, g_hhi);
    cudaGetSymbolAddress((void**)&p_hlo, g_hlo);
    cudaGetSymbolAddress((void**)&p_wth, g_wth);
    cudaGetSymbolAddress((void**)&p_wtl, g_wtl);

    cudaFuncSetAttribute(mgemm_kernel<0>, cudaFuncAttributeMaxDynamicSharedMemorySize, MG_SMEM);
    cudaFuncSetAttribute(mgemm_kernel<1>, cudaFuncAttributeMaxDynamicSharedMemorySize, MG_SMEM);
    cudaFuncSetAttribute(mgemm_kernel<2>, cudaFuncAttributeMaxDynamicSharedMemorySize, MG_SMEM);
    cudaFuncSetAttribute(mgemm_kernel<3>, cudaFuncAttributeMaxDynamicSharedMemorySize, MG_SMEM);
    cudaFuncSetAttribute(attn_kernel,     cudaFuncAttributeMaxDynamicSharedMemorySize, ATT_SMEM);

    // L1: weights transpose+split
    wtrans_all_kernel<<<768, dim3(32,8)>>>(qkv_w, wo_w, mlp_w1, mlp_w2);
    // L2: LN1 -> window layout, bf16 split
    ln_kernel<true><<<PIX/8, 256>>>(x, ln1_g, ln1_b, p_ahi, p_alo);
    // L3: window means
    winmeanx_kernel<<<NWIN, 256>>>();
    // L4: qkv GEMM (the slot ncu captures)
    mgemm_kernel<0><<<dim3(6, 196), 256, MG_SMEM>>>(p_ahi, p_alo, p_wth+OFF_QKV, p_wtl+OFF_QKV,
                                                    qkv_b, nullptr, p_qkv, nullptr, nullptr, 768, 256);
    // L5-L6: routing path
    winproj_kernel<<<dim3(49,2), 256>>>(qkv_w, qkv_b);
    logit_topk_kernel<<<NWIN, 256>>>();
    // L7: lepe, L8: attention (writes g_ahi/g_alo = attn+lepe split)
    lepe_kernel<<<dim3(49, 4, 8), 256>>>(lepe_w, lepe_b);
    attn_kernel<<<dim3(NWIN, 8), 256, ATT_SMEM>>>();
    // L9: wo GEMM + residual + layout remap
    mgemm_kernel<1><<<dim3(2, 196), 256, MG_SMEM>>>(p_ahi, p_alo, p_wth+OFF_WO, p_wtl+OFF_WO,
                                                    wo_b, x, p_x2, nullptr, nullptr, 256, 256);
    // L10: LN2 -> bf16 split
    ln_kernel<false><<<PIX/8, 256>>>(p_x2, ln2_g, ln2_b, p_ahi, p_alo);
    // L11: mlp1 + gelu -> bf16 split
    mgemm_kernel<2><<<dim3(8, 196), 256, MG_SMEM>>>(p_ahi, p_alo, p_wth+OFF_M1, p_wtl+OFF_M1,
                                                    mlp_b1, nullptr, nullptr, p_hhi, p_hlo, 1024, 256);
    // L12: mlp2 + residual -> out
    mgemm_kernel<3><<<dim3(2, 196), 256, MG_SMEM>>>(p_hhi, p_hlo, p_wth+OFF_M2, p_wtl+OFF_M2,
                                                    mlp_b2, p_x2, out, nullptr, nullptr, 256, 1024);
}

// round 17
// speedup vs baseline: 1.0442x; 1.0442x over previous
#include <cuda_runtime.h>
#include <cuda_bf16.h>
#include <math.h>
#include <stdint.h>

#define PIX 25088           // 8*56*56
#define NWIN 392            // 8*49

// ---------------- device scratch ----------------
__device__ __align__(128) __nv_bfloat16 g_qkvh[PIX*768];  // qkv bf16, window-major rows
__device__ __align__(128) __nv_bfloat16 g_ahi[PIX*256];   // generic A operand hi (reused)
__device__ __align__(128) __nv_bfloat16 g_alo[PIX*256];   // generic A operand lo
__device__ __align__(128) float g_xbar[NWIN*256];
__device__ __align__(128) float g_qwin[NWIN*256];
__device__ __align__(128) float g_kwin[NWIN*256];
__device__ __align__(128) int   g_ridx[NWIN*4];
__device__ __align__(128) float g_lepe[PIX*256];          // window-major
__device__ __align__(128) float g_x2  [PIX*256];          // image-major residual stream
__device__ __align__(128) __nv_bfloat16 g_hhi[PIX*1024];  // mlp hidden hi
__device__ __align__(128) __nv_bfloat16 g_hlo[PIX*1024];  // mlp hidden lo
__device__ __align__(128) __nv_bfloat16 g_wth[786432];    // transposed weights hi [N][K]
__device__ __align__(128) __nv_bfloat16 g_wtl[786432];    // transposed weights lo
#define OFF_QKV 0
#define OFF_WO  196608
#define OFF_M1  262144
#define OFF_M2  524288

// ---------------- layout maps ----------------
__device__ __forceinline__ int img2win(int pix){
    int n = pix / 3136, r = pix % 3136;
    int y = r / 56, x = r % 56;
    return (n*49 + (y>>3)*7 + (x>>3))*64 + ((y&7)<<3) + (x&7);
}
__device__ __forceinline__ int win2img(int rw){
    int n = rw / 3136, r = rw % 3136;
    int p = r >> 6, q = r & 63;
    int y = ((p/7)<<3) + (q>>3), x = ((p%7)<<3) + (q&7);
    return n*3136 + y*56 + x;
}

// ---------------- helpers ----------------
__device__ __forceinline__ uint32_t smem_u32(const void* p){
    uint32_t a;
    asm("{ .reg .u64 t; cvta.to.shared.u64 t, %1; cvt.u32.u64 %0, t; }" : "=r"(a) : "l"(p));
    return a;
}
__device__ __forceinline__ void cp16(uint32_t saddr, const void* gaddr){
    asm volatile("cp.async.cg.shared.global [%0], [%1], 16;" :: "r"(saddr), "l"(gaddr));
}
__device__ __forceinline__ void ldmA(uint32_t* a, uint32_t addr){
    asm volatile("ldmatrix.sync.aligned.m8n8.x4.shared.b16 {%0,%1,%2,%3}, [%4];"
        : "=r"(a[0]),"=r"(a[1]),"=r"(a[2]),"=r"(a[3]) : "r"(addr));
}
__device__ __forceinline__ void ldmB(uint32_t* b, uint32_t addr){
    asm volatile("ldmatrix.sync.aligned.m8n8.x2.shared.b16 {%0,%1}, [%2];"
        : "=r"(b[0]),"=r"(b[1]) : "r"(addr));
}
__device__ __forceinline__ void mma16816(float* c, const uint32_t* a, const uint32_t* b){
    asm volatile("mma.sync.aligned.m16n8k16.row.col.f32.bf16.bf16.f32 "
        "{%0,%1,%2,%3}, {%4,%5,%6,%7}, {%8,%9}, {%0,%1,%2,%3};"
        : "+f"(c[0]),"+f"(c[1]),"+f"(c[2]),"+f"(c[3])
        : "r"(a[0]),"r"(a[1]),"r"(a[2]),"r"(a[3]), "r"(b[0]),"r"(b[1]));
}
__device__ __forceinline__ uint32_t packbf2(__nv_bfloat16 a, __nv_bfloat16 b){
    return (uint32_t)__bfloat16_as_ushort(a) | ((uint32_t)__bfloat16_as_ushort(b) << 16);
}
__device__ __forceinline__ void split8(const float* v, uint4& uh, uint4& ul){
    __nv_bfloat16 h[8], l[8];
    #pragma unroll
    for (int j = 0; j < 8; j++){
        h[j] = __float2bfloat16(v[j]);
        l[j] = __float2bfloat16(v[j] - __bfloat162float(h[j]));
    }
    uh = make_uint4(packbf2(h[0],h[1]), packbf2(h[2],h[3]), packbf2(h[4],h[5]), packbf2(h[6],h[7]));
    ul = make_uint4(packbf2(l[0],l[1]), packbf2(l[2],l[3]), packbf2(l[4],l[5]), packbf2(l[6],l[7]));
}

// ---------------- LayerNorm -> bf16 hi/lo ----------------
template<bool REMAP>
__global__ void ln_kernel(const float* __restrict__ in, const float* __restrict__ g,
                          const float* __restrict__ b,
                          __nv_bfloat16* __restrict__ oh, __nv_bfloat16* __restrict__ ol){
    int warp = threadIdx.x >> 5, lane = threadIdx.x & 31;
    int pix = blockIdx.x * 8 + warp;
    const float* row = in + (size_t)pix * 256;
    int c0 = lane * 8;
    float4 v0 = *(const float4*)(row + c0);
    float4 v1 = *(const float4*)(row + c0 + 4);
    float vals[8] = {v0.x,v0.y,v0.z,v0.w,v1.x,v1.y,v1.z,v1.w};
    float s = 0.f, ss = 0.f;
    #pragma unroll
    for (int u = 0; u < 8; u++){ s += vals[u]; ss += vals[u]*vals[u]; }
    #pragma unroll
    for (int o = 16; o; o >>= 1){
        s  += __shfl_xor_sync(0xffffffffu, s,  o);
        ss += __shfl_xor_sync(0xffffffffu, ss, o);
    }
    float mu  = s * (1.f/256.f);
    float var = ss * (1.f/256.f) - mu*mu;
    float inv = rsqrtf(var + 1e-6f);
    int orow = REMAP ? img2win(pix) : pix;
    float ov[8];
    #pragma unroll
    for (int u = 0; u < 8; u++) ov[u] = (vals[u]-mu)*inv*g[c0+u] + b[c0+u];
    uint4 uh, ul;
    split8(ov, uh, ul);
    *(uint4*)&oh[(size_t)orow*256 + c0] = uh;
    *(uint4*)&ol[(size_t)orow*256 + c0] = ul;
}

// ---------------- fused weight transpose + split (ALL matrices, one launch) -------
__global__ void wtrans_all_kernel(const float* __restrict__ qkv_w, const float* __restrict__ wo_w,
                                  const float* __restrict__ m1_w,  const float* __restrict__ m2_w){
    __shared__ float t[32][33];
    int b = blockIdx.x;
    const float* w; int K, N, off;
    if (b < 192)      { w = qkv_w;       K = 256;  N = 768;  off = OFF_QKV; }
    else if (b < 256) { b -= 192; w = wo_w; K = 256; N = 256; off = OFF_WO; }
    else if (b < 512) { b -= 256; w = m1_w; K = 256; N = 1024; off = OFF_M1; }
    else              { b -= 512; w = m2_w; K = 1024; N = 256; off = OFF_M2; }
    int ntiles = N / 32;
    int n0 = (b % ntiles) * 32, k0 = (b / ntiles) * 32;
    int tx = threadIdx.x, ty = threadIdx.y;
    for (int r = ty; r < 32; r += 8) t[r][tx] = w[(size_t)(k0+r)*N + n0+tx];
    __syncthreads();
    for (int r = ty; r < 32; r += 8){
        float v = t[tx][r];
        __nv_bfloat16 h = __float2bfloat16(v);
        g_wth[off + (size_t)(n0+r)*K + k0+tx] = h;
        g_wtl[off + (size_t)(n0+r)*K + k0+tx] = __float2bfloat16(v - __bfloat162float(h));
    }
}

// ---------------- window mean of x (hi+lo, exact routing path) ----------------
__global__ void winmeanx_kernel(){
    int np = blockIdx.x, c = threadIdx.x;
    float s = 0.f;
    #pragma unroll 4
    for (int r = 0; r < 64; r++){
        size_t i = (size_t)(np*64+r)*256 + c;
        s += __bfloat162float(g_ahi[i]) + __bfloat162float(g_alo[i]);
    }
    g_xbar[np*256 + c] = s * (1.f/64.f);
}

// ---------------- q_win/k_win: 8 windows per block, q/k split over grid.y ----------
__global__ void winproj_kernel(const float* __restrict__ qkv_w, const float* __restrict__ qkv_b){
    __shared__ float sx[8][256];
    int b0 = blockIdx.x * 8;
    int qk = blockIdx.y;              // 0 = q, 1 = k
    int c = threadIdx.x;
    #pragma unroll
    for (int j = 0; j < 8; j++) sx[j][c] = g_xbar[(b0+j)*256 + c];
    __syncthreads();
    float bb = qkv_b[qk*256 + c];
    float a[8];
    #pragma unroll
    for (int j = 0; j < 8; j++) a[j] = bb;
    for (int d = 0; d < 256; d++){
        float wv = qkv_w[d*768 + qk*256 + c];
        #pragma unroll
        for (int j = 0; j < 8; j++) a[j] += sx[j][d]*wv;
    }
    float* outp = qk ? g_kwin : g_qwin;
    #pragma unroll
    for (int j = 0; j < 8; j++) outp[(b0+j)*256 + c] = a[j];
}

// ---------------- logits + top-4 (one block per window) ----------------
__global__ void logit_topk_kernel(){
    __shared__ float sq[256];
    __shared__ float sl[64];
    int np = blockIdx.x, n = np / 49;
    int tid = threadIdx.x;
    sq[tid] = g_qwin[np*256 + tid];
    if (tid < 64) sl[tid] = -1e30f;
    __syncthreads();
    int t = tid >> 2, part = tid & 3;
    int tc = (t < 49) ? t : 48;
    const float* kr = &g_kwin[(size_t)(n*49 + tc)*256 + part*64];
    float acc = 0.f;
    #pragma unroll 8
    for (int c = 0; c < 64; c++) acc += sq[part*64 + c] * kr[c];
    acc += __shfl_xor_sync(0xffffffffu, acc, 1);
    acc += __shfl_xor_sync(0xffffffffu, acc, 2);
    if (part == 0 && t < 49) sl[t] = acc * 0.0625f;
    __syncthreads();
    if (tid == 0){
        float bv[4] = {-1e30f,-1e30f,-1e30f,-1e30f};
        int   bi[4] = {0,0,0,0};
        for (int k = 0; k < 49; k++){
            float v = sl[k];
            if (v > bv[3]){
                int pos = 3;
                while (pos > 0 && v > bv[pos-1]) pos--;
                for (int sft = 3; sft > pos; sft--){ bv[sft]=bv[sft-1]; bi[sft]=bi[sft-1]; }
                bv[pos] = v; bi[pos] = k;
            }
        }
        #pragma unroll
        for (int s = 0; s < 4; s++) g_ridx[np*4 + s] = bi[s];
    }
}

// ---------------- lepe: 5x5 depthwise conv, smem-halo tiled (bf16 v input) --------
__global__ void __launch_bounds__(256) lepe_kernel(const float* __restrict__ w, const float* __restrict__ b){
    __shared__ float halo[144*68];
    __shared__ float ws[25*64];
    __shared__ float wb[64];
    int wi = blockIdx.x;
    int cg = blockIdx.y;
    int n  = blockIdx.z;
    int wy = wi / 7, wx = wi % 7;
    int tid = threadIdx.x;
    for (int i = tid; i < 1600; i += 256)
        ws[i] = w[(i>>6)*256 + cg*64 + (i&63)];
    if (tid < 64) wb[tid] = b[cg*64 + tid];
    for (int i = tid; i < 2304; i += 256){
        int hp = i >> 4, cs = i & 15;
        int hy = hp / 12, hx = hp % 12;
        int y = wy*8 - 2 + hy, x = wx*8 - 2 + hx;
        float4 v = make_float4(0.f,0.f,0.f,0.f);
        if ((unsigned)y < 56u && (unsigned)x < 56u){
            int rw = ((n*49 + (y>>3)*7 + (x>>3))<<6) + ((y&7)<<3) + (x&7);
            const __nv_bfloat162* vp = (const __nv_bfloat162*)&g_qkvh[(size_t)rw*768 + 512 + cg*64 + cs*4];
            float2 f0 = __bfloat1622float2(vp[0]);
            float2 f1 = __bfloat1622float2(vp[1]);
            v = make_float4(f0.x, f0.y, f1.x, f1.y);
        }
        *(float4*)&halo[hp*68 + cs*4] = v;
    }
    __syncthreads();
    int p = tid >> 2, q = tid & 3;
    int py = p >> 3, px = p & 7;
    float acc[16];
    #pragma unroll
    for (int j = 0; j < 16; j++) acc[j] = wb[q*16 + j];
    #pragma unroll
    for (int ky = 0; ky < 5; ky++)
        #pragma unroll
        for (int kx = 0; kx < 5; kx++){
            const float* hp2 = &halo[((py+ky)*12 + px+kx)*68 + q*16];
            const float* wp  = &ws[(ky*5+kx)*64 + q*16];
            #pragma unroll
            for (int j = 0; j < 16; j++) acc[j] += hp2[j]*wp[j];
        }
    int rw = ((n*49 + wy*7 + wx)<<6) + (py<<3) + px;
    float* outp = &g_lepe[(size_t)rw*256 + cg*64 + q*16];
    #pragma unroll
    for (int j = 0; j < 4; j++)
        *(float4*)&outp[j*4] = make_float4(acc[j*4],acc[j*4+1],acc[j*4+2],acc[j*4+3]);
}

// ---------------- attention: register-tiled, bf16 qkv in, fused lepe+split out ----
#define ATT_ST 34
#define ATT_SMEM ((64*ATT_ST + 2*256*ATT_ST + 64*68)*4)   // 95744 B
__global__ void __launch_bounds__(256,2) attn_kernel(){
    int np = blockIdx.x;
    int m  = blockIdx.y;
    int n  = np / 49;
    int tid = threadIdx.x;
    extern __shared__ float sm[];
    float* sq = sm;
    float* sk = sq + 64*ATT_ST;
    float* sv = sk + 256*ATT_ST;
    float* sp = sv + 256*ATT_ST;
    int base = np * 64;

    // q: 64 rows x 32 ch, bf162 loads
    for (int idx = tid; idx < 1024; idx += 256){
        int r = idx >> 4, d2 = (idx & 15)*2;
        __nv_bfloat162 t = *(const __nv_bfloat162*)&g_qkvh[(size_t)(base+r)*768 + m*32 + d2];
        float2 f = __bfloat1622float2(t);
        sq[r*ATT_ST + d2] = f.x; sq[r*ATT_ST + d2+1] = f.y;
    }
    #pragma unroll
    for (int s4 = 0; s4 < 4; s4++){
        int wsel = g_ridx[np*4 + s4];
        int sb = (n*49 + wsel) * 64;
        for (int idx = tid; idx < 1024; idx += 256){
            int r = idx >> 4, d2 = (idx & 15)*2;
            int kk = s4*64 + r;
            __nv_bfloat162 tk = *(const __nv_bfloat162*)&g_qkvh[(size_t)(sb+r)*768 + 256 + m*32 + d2];
            __nv_bfloat162 tv = *(const __nv_bfloat162*)&g_qkvh[(size_t)(sb+r)*768 + 512 + m*32 + d2];
            float2 fk = __bfloat1622float2(tk);
            float2 fv = __bfloat1622float2(tv);
            sk[kk*ATT_ST + d2] = fk.x; sk[kk*ATT_ST + d2+1] = fk.y;
            sv[kk*ATT_ST + d2] = fv.x; sv[kk*ATT_ST + d2+1] = fv.y;
        }
    }
    __syncthreads();

    const int rowg = tid >> 3;
    const int colg = tid & 7;
    const int r0 = rowg*2, r1 = r0 + 1;

    float sc[2][32];
    #pragma unroll
    for (int j = 0; j < 32; j++){ sc[0][j] = 0.f; sc[1][j] = 0.f; }
    for (int cc = 0; cc < 16; cc++){
        float2 q0 = *(float2*)&sq[r0*ATT_ST + cc*2];
        float2 q1 = *(float2*)&sq[r1*ATT_ST + cc*2];
        #pragma unroll
        for (int j = 0; j < 32; j++){
            float2 kv = *(float2*)&sk[(j*8+colg)*ATT_ST + cc*2];
            sc[0][j] += q0.x*kv.x + q0.y*kv.y;
            sc[1][j] += q1.x*kv.x + q1.y*kv.y;
        }
    }
    float mx0 = -1e30f, mx1 = -1e30f;
    #pragma unroll
    for (int j = 0; j < 32; j++){
        sc[0][j] *= 0.0625f; sc[1][j] *= 0.0625f;
        mx0 = fmaxf(mx0, sc[0][j]); mx1 = fmaxf(mx1, sc[1][j]);
    }
    #pragma unroll
    for (int o = 4; o; o >>= 1){
        mx0 = fmaxf(mx0, __shfl_xor_sync(0xffffffffu, mx0, o));
        mx1 = fmaxf(mx1, __shfl_xor_sync(0xffffffffu, mx1, o));
    }
    float s0 = 0.f, s1 = 0.f;
    #pragma unroll
    for (int j = 0; j < 32; j++){
        sc[0][j] = __expf(sc[0][j] - mx0); s0 += sc[0][j];
        sc[1][j] = __expf(sc[1][j] - mx1); s1 += sc[1][j];
    }
    #pragma unroll
    for (int o = 4; o; o >>= 1){
        s0 += __shfl_xor_sync(0xffffffffu, s0, o);
        s1 += __shfl_xor_sync(0xffffffffu, s1, o);
    }
    float i0 = 1.f/s0, i1 = 1.f/s1;
    #pragma unroll
    for (int j = 0; j < 32; j++){ sc[0][j] *= i0; sc[1][j] *= i1; }

    const int chg = (tid >> 1) & 3;
    const int ksp = tid & 1;
    float oa[2][8];
    #pragma unroll
    for (int j = 0; j < 8; j++){ oa[0][j] = 0.f; oa[1][j] = 0.f; }

    #pragma unroll
    for (int c = 0; c < 4; c++){
        __syncthreads();
        #pragma unroll
        for (int jj = 0; jj < 8; jj++){
            int kl = jj*8 + colg;
            sp[r0*68 + kl] = sc[0][c*8 + jj];
            sp[r1*68 + kl] = sc[1][c*8 + jj];
        }
        __syncthreads();
        #pragma unroll 8
        for (int kk = 0; kk < 32; kk++){
            int kl = kk*2 + ksp;
            float p0 = sp[r0*68 + kl];
            float p1 = sp[r1*68 + kl];
            const float* vr = &sv[(c*64 + kl)*ATT_ST + chg*8];
            #pragma unroll
            for (int j2 = 0; j2 < 4; j2++){
                float2 vv = *(float2*)&vr[j2*2];
                oa[0][j2*2]   += p0*vv.x; oa[0][j2*2+1] += p0*vv.y;
                oa[1][j2*2]   += p1*vv.x; oa[1][j2*2+1] += p1*vv.y;
            }
        }
    }
    #pragma unroll
    for (int i2 = 0; i2 < 2; i2++)
        #pragma unroll
        for (int j = 0; j < 8; j++)
            oa[i2][j] += __shfl_xor_sync(0xffffffffu, oa[i2][j], 1);

    if (ksp == 0){
        #pragma unroll
        for (int i2 = 0; i2 < 2; i2++){
            int row = base + r0 + i2;
            int ch0 = m*32 + chg*8;
            const float* lp = &g_lepe[(size_t)row*256 + ch0];
            float v[8];
            #pragma unroll
            for (int j = 0; j < 8; j++) v[j] = oa[i2][j] + lp[j];
            uint4 uh, ul;
            split8(v, uh, ul);
            *(uint4*)&g_ahi[(size_t)row*256 + ch0] = uh;
            *(uint4*)&g_alo[(size_t)row*256 + ch0] = ul;
        }
    }
}

// ---------------- mma.sync split-bf16 GEMM: merged 3-pass w/ fragment reuse -------
// MODE 0: outh = bf16(A@B + bias)                 (qkv -> bf16 intermediate)
// MODE 1: outf[win2img] = res + A@B + bias        (wo + residual, layout remap)
// MODE 2: outh/outl = split(gelu(A@B + bias))      (mlp1)
// MODE 3: outf = res + A@B + bias                  (mlp2 -> final out)
#define LDH 40
#define MG_TILE (128*LDH*2)          // 10240 B per tile
#define MG_STAGE (4*MG_TILE)         // 40960 B
#define MG_SMEM (2*MG_STAGE)         // 81920 B
template<int MODE>
__global__ void __launch_bounds__(256,2) mgemm_kernel(
    const __nv_bfloat16* __restrict__ Ahi, const __nv_bfloat16* __restrict__ Alo,
    const __nv_bfloat16* __restrict__ Bhi, const __nv_bfloat16* __restrict__ Blo,
    const float* __restrict__ bias, const float* __restrict__ res,
    float* __restrict__ outf, __nv_bfloat16* __restrict__ outh, __nv_bfloat16* __restrict__ outl,
    int N, int K)
{
    extern __shared__ __align__(128) char dsm[];
    const uint32_t sbase = smem_u32(dsm);
    const int tid = threadIdx.x, w = tid >> 5, lane = tid & 31;
    const int m0 = blockIdx.y * 128, n0 = blockIdx.x * 128;
    const int wm = (w >> 2) * 64, wn = (w & 3) * 32;
    const int kch = K / 32;

    float acc[4][4][4];
    #pragma unroll
    for (int i = 0; i < 4; i++)
        #pragma unroll
        for (int j = 0; j < 4; j++)
            #pragma unroll
            for (int q = 0; q < 4; q++) acc[i][j][q] = 0.f;

    const int rA = tid >> 2;
    const int sg = (tid & 3) * 8;

    auto issue = [&](int c, int s){
        int ko = c * 32;
        uint32_t st = sbase + s*MG_STAGE;
        uint32_t so0 = (uint32_t)(rA*LDH + sg) * 2;
        uint32_t so1 = (uint32_t)((64+rA)*LDH + sg) * 2;
        cp16(st + so0,             Ahi + (size_t)(m0+rA)*K + ko + sg);
        cp16(st + so1,             Ahi + (size_t)(m0+64+rA)*K + ko + sg);
        cp16(st + MG_TILE + so0,   Alo + (size_t)(m0+rA)*K + ko + sg);
        cp16(st + MG_TILE + so1,   Alo + (size_t)(m0+64+rA)*K + ko + sg);
        cp16(st + 2*MG_TILE + so0, Bhi + (size_t)(n0+rA)*K + ko + sg);
        cp16(st + 2*MG_TILE + so1, Bhi + (size_t)(n0+64+rA)*K + ko + sg);
        cp16(st + 3*MG_TILE + so0, Blo + (size_t)(n0+rA)*K + ko + sg);
        cp16(st + 3*MG_TILE + so1, Blo + (size_t)(n0+64+rA)*K + ko + sg);
        asm volatile("cp.async.commit_group;");
    };

    issue(0, 0);

    for (int c = 0; c < kch; c++){
        int s = c & 1;
        if (c + 1 < kch){
            issue(c+1, s ^ 1);
            asm volatile("cp.async.wait_group 1;");
        } else {
            asm volatile("cp.async.wait_group 0;");
        }
        __syncthreads();

        uint32_t st = sbase + s*MG_STAGE;
        #pragma unroll
        for (int ks = 0; ks < 2; ks++){
            const int kk = ks * 16;
            const uint32_t aoff = (uint32_t)((wm + (lane & 15))*LDH + kk + ((lane >> 4) & 1)*8) * 2;
            const uint32_t boff = (uint32_t)((wn + (lane & 7))*LDH + kk + ((lane >> 3) & 1)*8) * 2;

            uint32_t afr[4][4];
            uint32_t bhi[4][2];
            uint32_t tfr[4][4];
            // pass 0: Ahi x Bhi
            #pragma unroll
            for (int mt = 0; mt < 4; mt++) ldmA(afr[mt], st + aoff + mt*16*LDH*2);
            #pragma unroll
            for (int nt = 0; nt < 4; nt++) ldmB(bhi[nt], st + 2*MG_TILE + boff + nt*8*LDH*2);
            #pragma unroll
            for (int mt = 0; mt < 4; mt++)
                #pragma unroll
                for (int nt = 0; nt < 4; nt++)
                    mma16816(acc[mt][nt], afr[mt], bhi[nt]);
            // pass 1: Ahi x Blo
            #pragma unroll
            for (int nt = 0; nt < 4; nt++) ldmB(&tfr[nt][0], st + 3*MG_TILE + boff + nt*8*LDH*2);
            #pragma unroll
            for (int mt = 0; mt < 4; mt++)
                #pragma unroll
                for (int nt = 0; nt < 4; nt++)
                    mma16816(acc[mt][nt], afr[mt], &tfr[nt][0]);
            // pass 2: Alo x Bhi
            #pragma unroll
            for (int mt = 0; mt < 4; mt++) ldmA(afr[mt], st + MG_TILE + aoff + mt*16*LDH*2);
            #pragma unroll
            for (int mt = 0; mt < 4; mt++)
                #pragma unroll
                for (int nt = 0; nt < 4; nt++)
                    mma16816(acc[mt][nt], afr[mt], bhi[nt]);
        }
        __syncthreads();
    }

    #pragma unroll
    for (int mt = 0; mt < 4; mt++){
        int r0 = m0 + wm + mt*16 + (lane >> 2);
        int r1 = r0 + 8;
        int o0 = (MODE == 1) ? win2img(r0) : r0;
        int o1 = (MODE == 1) ? win2img(r1) : r1;
        #pragma unroll
        for (int nt = 0; nt < 4; nt++){
            int col = n0 + wn + nt*8 + (lane & 3)*2;
            float b0 = bias[col], b1 = bias[col+1];
            float v00 = acc[mt][nt][0] + b0, v01 = acc[mt][nt][1] + b1;
            float v10 = acc[mt][nt][2] + b0, v11 = acc[mt][nt][3] + b1;
            if (MODE == 0){
                *(uint32_t*)&outh[(size_t)o0*N + col] = packbf2(__float2bfloat16(v00), __float2bfloat16(v01));
                *(uint32_t*)&outh[(size_t)o1*N + col] = packbf2(__float2bfloat16(v10), __float2bfloat16(v11));
            } else if (MODE == 2){
                v00 = 0.5f*v00*(1.f + erff(v00*0.70710678118654752f));
                v01 = 0.5f*v01*(1.f + erff(v01*0.70710678118654752f));
                v10 = 0.5f*v10*(1.f + erff(v10*0.70710678118654752f));
                v11 = 0.5f*v11*(1.f + erff(v11*0.70710678118654752f));
                __nv_bfloat16 h00 = __float2bfloat16(v00), h01 = __float2bfloat16(v01);
                __nv_bfloat16 h10 = __float2bfloat16(v10), h11 = __float2bfloat16(v11);
                *(uint32_t*)&outh[(size_t)o0*N + col] = packbf2(h00, h01);
                *(uint32_t*)&outh[(size_t)o1*N + col] = packbf2(h10, h11);
                *(uint32_t*)&outl[(size_t)o0*N + col] = packbf2(
                    __float2bfloat16(v00 - __bfloat162float(h00)),
                    __float2bfloat16(v01 - __bfloat162float(h01)));
                *(uint32_t*)&outl[(size_t)o1*N + col] = packbf2(
                    __float2bfloat16(v10 - __bfloat162float(h10)),
                    __float2bfloat16(v11 - __bfloat162float(h11)));
            } else {
                v00 += res[(size_t)o0*N + col];   v01 += res[(size_t)o0*N + col + 1];
                v10 += res[(size_t)o1*N + col];   v11 += res[(size_t)o1*N + col + 1];
                *(float2*)&outf[(size_t)o0*N + col] = make_float2(v00, v01);
                *(float2*)&outf[(size_t)o1*N + col] = make_float2(v10, v11);
            }
        }
    }
}

// ---------------- launch ----------------
extern "C" void kernel_launch(void* const* d_in, const int* in_sizes, int n_in,
                              void* d_out, int out_size)
{
    const float* x      = (const float*)d_in[0];
    const float* ln1_g  = (const float*)d_in[1];
    const float* ln1_b  = (const float*)d_in[2];
    const float* qkv_w  = (const float*)d_in[3];
    const float* qkv_b  = (const float*)d_in[4];
    const float* lepe_w = (const float*)d_in[5];
    const float* lepe_b = (const float*)d_in[6];
    const float* wo_w   = (const float*)d_in[7];
    const float* wo_b   = (const float*)d_in[8];
    const float* ln2_g  = (const float*)d_in[9];
    const float* ln2_b  = (const float*)d_in[10];
    const float* mlp_w1 = (const float*)d_in[11];
    const float* mlp_b1 = (const float*)d_in[12];
    const float* mlp_w2 = (const float*)d_in[13];
    const float* mlp_b2 = (const float*)d_in[14];
    float* out = (float*)d_out;

    float *p_x2;
    __nv_bfloat16 *p_qkvh, *p_ahi, *p_alo, *p_hhi, *p_hlo, *p_wth, *p_wtl;
    cudaGetSymbolAddress((void**)&p_qkvh, g_qkvh);
    cudaGetSymbolAddress((void**)&p_x2,  g_x2);
    cudaGetSymbolAddress((void**)&p_ahi, g_ahi);
    cudaGetSymbolAddress((void**)&p_alo, g_alo);
    cudaGetSymbolAddress((void**)&p_hhi, g_hhi);
    cudaGetSymbolAddress((void**)&p_hlo, g_hlo);
    cudaGetSymbolAddress((void**)&p_wth, g_wth);
    cudaGetSymbolAddress((void**)&p_wtl, g_wtl);

    cudaFuncSetAttribute(mgemm_kernel<0>, cudaFuncAttributeMaxDynamicSharedMemorySize, MG_SMEM);
    cudaFuncSetAttribute(mgemm_kernel<1>, cudaFuncAttributeMaxDynamicSharedMemorySize, MG_SMEM);
    cudaFuncSetAttribute(mgemm_kernel<2>, cudaFuncAttributeMaxDynamicSharedMemorySize, MG_SMEM);
    cudaFuncSetAttribute(mgemm_kernel<3>, cudaFuncAttributeMaxDynamicSharedMemorySize, MG_SMEM);
    cudaFuncSetAttribute(attn_kernel,     cudaFuncAttributeMaxDynamicSharedMemorySize, ATT_SMEM);

    // L1: weights transpose+split
    wtrans_all_kernel<<<768, dim3(32,8)>>>(qkv_w, wo_w, mlp_w1, mlp_w2);
    // L2: LN1 -> window layout, bf16 split
    ln_kernel<true><<<PIX/8, 256>>>(x, ln1_g, ln1_b, p_ahi, p_alo);
    // L3: window means
    winmeanx_kernel<<<NWIN, 256>>>();
    // L4: qkv GEMM -> bf16 intermediate (the slot ncu captures)
    mgemm_kernel<0><<<dim3(6, 196), 256, MG_SMEM>>>(p_ahi, p_alo, p_wth+OFF_QKV, p_wtl+OFF_QKV,
                                                    qkv_b, nullptr, nullptr, p_qkvh, nullptr, 768, 256);
    // L5-L6: routing path (exact fp32)
    winproj_kernel<<<dim3(49,2), 256>>>(qkv_w, qkv_b);
    logit_topk_kernel<<<NWIN, 256>>>();
    // L7: lepe, L8: attention (writes g_ahi/g_alo = attn+lepe split)
    lepe_kernel<<<dim3(49, 4, 8), 256>>>(lepe_w, lepe_b);
    attn_kernel<<<dim3(NWIN, 8), 256, ATT_SMEM>>>();
    // L9: wo GEMM + residual + layout remap
    mgemm_kernel<1><<<dim3(2, 196), 256, MG_SMEM>>>(p_ahi, p_alo, p_wth+OFF_WO, p_wtl+OFF_WO,
                                                    wo_b, x, p_x2, nullptr, nullptr, 256, 256);
    // L10: LN2 -> bf16 split
    ln_kernel<false><<<PIX/8, 256>>>(p_x2, ln2_g, ln2_b, p_ahi, p_alo);
    // L11: mlp1 + gelu -> bf16 split
    mgemm_kernel<2><<<dim3(8, 196), 256, MG_SMEM>>>(p_ahi, p_alo, p_wth+OFF_M1, p_wtl+OFF_M1,
                                                    mlp_b1, nullptr, nullptr, p_hhi, p_hlo, 1024, 256);
    // L12: mlp2 + residual -> out
    mgemm_kernel<3><<<dim3(2, 196), 256, MG_SMEM>>>(p_hhi, p_hlo, p_wth+OFF_M2, p_wtl+OFF_M2,
                                                    mlp_b2, p_x2, out, nullptr, nullptr, 256, 1024);
}